// round 10
// baseline (speedup 1.0000x reference)
#include <cuda_runtime.h>
#include <math.h>

#define BATCH 2048
#define LEN   4096
#define NT    448              // 14 warps: x-threads [0,218), y-threads [224,442)
#define YT0   224
#define W     19
#define NBLK  218              // 218*19 = 4142 >= 20+4096+19
#define PRE   32               // front guard (-inf), covers reads down to p=-19
#define ASZ   4208             // PRE + 4142 + tail guard, 16B-aligned
#define DIDX  52               // smem index of signal element i=0 (p=20+i, +PRE)

__device__ float4   g_rowbuf[BATCH];
__device__ unsigned g_count;

// ---------------- warp reductions ----------------
__device__ __forceinline__ double wredD(double v) {
    #pragma unroll
    for (int o = 16; o; o >>= 1) v += __shfl_down_sync(0xffffffffu, v, o);
    return v;
}
__device__ __forceinline__ int wredI(int v) {
    #pragma unroll
    for (int o = 16; o; o >>= 1) v += __shfl_down_sync(0xffffffffu, v, o);
    return v;
}

// ---------------- register-resident van Herk block, dense d10+d20 -----------
// Thread owns padded block [s, s+19). Full halo chains:
//   Sl[k] = max(B[k-19 .. -1]),  Pr[k] = max(B[19 .. 19+k])
// peak10: strict local max && v >= pooled19; peak20 = peak10 && v>=Sl[j]
// && v>=Pr[j] && v>=Mfull. -inf guards exclude pads; i=0 / i=LEN-1 false
// positives cleared by mask bit at their owning (s, j) slots.
__device__ __forceinline__ void processBlock(const float* __restrict__ A, int s,
                                             unsigned& mask, int& cnt20) {
    const float* B = A + PRE + s;    // B[j] = value at p = s+j

    float c[W];
    #pragma unroll
    for (int j = 0; j < W; ++j) c[j] = B[j];

    float Sl[W];                     // Sl[k] = max(B[k-19 .. -1])
    Sl[18] = B[-1];
    #pragma unroll
    for (int k = 17; k >= 0; --k) Sl[k] = fmaxf(B[k - 19], Sl[k + 1]);

    float Pr[W];                     // Pr[k] = max(B[19 .. 19+k])
    Pr[0] = B[W];
    #pragma unroll
    for (int k = 1; k < W; ++k) Pr[k] = fmaxf(Pr[k - 1], B[W + k]);

    // seeds shared with the two m-chains; Mfull costs only 2 extra fmax
    float maxL = c[0];
    #pragma unroll
    for (int k = 1; k < 9; ++k) maxL = fmaxf(maxL, c[k]);      // max(c[0..8])
    float maxR = c[18];
    #pragma unroll
    for (int k = 17; k >= 10; --k) maxR = fmaxf(maxR, c[k]);   // max(c[10..18])
    const float Mfull = fmaxf(fmaxf(maxL, maxR), c[9]);

    unsigned m10 = 0u, m20 = 0u;

    // ---- left: j = 0..8, pooled19 = max( Sl[j+10], c[0..j+9] )
    {
        float m = maxL;
        #pragma unroll
        for (int j = 0; j <= 8; ++j) {
            m = fmaxf(m, c[j + 9]);                            // max(c[0..j+9])
            const float v = c[j];
            const float left = (j == 0) ? Sl[18] : c[j - 1];
            const float nb = fmaxf(left, c[j + 1]);
            if (v > nb && v >= fmaxf(m, Sl[j + 10])) {
                m10 |= (1u << j);
                if (v >= Sl[j] && v >= Pr[j] && v >= Mfull) m20 |= (1u << j);
            }
        }
    }
    // ---- center: j = 9, pooled19 = Mfull
    {
        const float v = c[9];
        const float nb = fmaxf(c[8], c[10]);
        if (v > nb && v >= Mfull) {
            m10 |= (1u << 9);
            if (v >= Sl[9] && v >= Pr[9]) m20 |= (1u << 9);
        }
    }
    // ---- right: j = 18..10, pooled19 = max( c[j-9..18], Pr[j-10] )
    {
        float m = maxR;
        #pragma unroll
        for (int t = 9; t >= 1; --t) {
            const int j = t + 9;                               // 18..10
            m = fmaxf(m, c[t]);                                // max(c[t..18])
            const float v = c[j];
            const float right = (j == W - 1) ? Pr[0] : c[j + 1];
            const float nb = fmaxf(c[j - 1], right);
            if (v > nb && v >= fmaxf(m, Pr[t - 1])) {
                m10 |= (1u << j);
                if (v >= Sl[j] && v >= Pr[j] && v >= Mfull) m20 |= (1u << j);
            }
        }
    }

    // edge corrections: i=0 lives at (s=19, j=1); i=LEN-1 at (s=4104, j=11)
    if (s == 19)   { m10 &= ~(1u << 1);  m20 &= ~(1u << 1);  }
    if (s == 4104) { m10 &= ~(1u << 11); m20 &= ~(1u << 11); }

    mask = m10;
    cnt20 = __popc(m20);
}

// ---------------- main kernel ----------------
__global__ void __launch_bounds__(NT, 2)
loss_kernel(const float* __restrict__ xg, const float* __restrict__ yg,
            float* __restrict__ out) {
    __shared__ __align__(16) float xs[ASZ];
    __shared__ __align__(16) float ys[ASZ];
    __shared__ unsigned mym[NBLK];
    __shared__ double redd[14 * 4];
    __shared__ int    redi[14 * 2];
    __shared__ int    s_isLast;

    const int tid  = threadIdx.x;
    const int lane = tid & 31;
    const int wid  = tid >> 5;
    const int row  = blockIdx.x;

    // -inf guards: idx [0,52) and [4148, 4208)  (112 slots)
    if (tid < 52 + (ASZ - 4148)) {
        const int idx = (tid < 52) ? tid : 4148 + (tid - 52);
        xs[idx] = -INFINITY;
        ys[idx] = -INFINITY;
    }

    // Phase 1: coalesced load + fp32 elementwise partials (dot + norms only;
    // sum of squared diffs recovered as nx - 2*dt + ny in fp64 at combine)
    const float4* x4 = (const float4*)(xg + (size_t)row * LEN);
    const float4* y4 = (const float4*)(yg + (size_t)row * LEN);
    float4* xs4 = (float4*)(xs + DIDX);
    float4* ys4 = (float4*)(ys + DIDX);
    float fdt = 0.f, fnx = 0.f, fny = 0.f;
    for (int j = tid; j < LEN / 4; j += NT) {
        float4 a = x4[j], b = y4[j];
        xs4[j] = a; ys4[j] = b;
        fdt += a.x*b.x + a.y*b.y + a.z*b.z + a.w*b.w;
        fnx += a.x*a.x + a.y*a.y + a.z*a.z + a.w*a.w;
        fny += b.x*b.x + b.y*b.y + b.z*b.z + b.w*b.w;
    }
    __syncthreads();                                   // B1: rows resident

    // Phase 2: x-warps and y-warps process their blocks concurrently
    int cx = 0, cy = 0;
    unsigned mx = 0u;
    if (tid < NBLK) {
        processBlock(xs, tid * W, mx, cx);
    } else if (tid >= YT0 && tid < YT0 + NBLK) {
        unsigned my;
        processBlock(ys, (tid - YT0) * W, my, cy);
        mym[tid - YT0] = my;
    }
    __syncthreads();                                   // B2: y masks visible

    // Phase 3: x-threads fuse the sparse p2p using the published y masks
    float fpp = 0.f;
    if (tid < NBLK) {
        const int base = DIDX - 20 + tid * W;          // smem idx of p = s
        unsigned my = mym[tid];
        unsigned un = mx | my;
        while (un) {
            const int j = __ffs(un) - 1;
            un &= un - 1;
            const float pkx = ((mx >> j) & 1u) ? xs[base + j] : 0.f;
            const float pky = ((my >> j) & 1u) ? ys[base + j] : 0.f;
            const float d = pkx - pky;
            fpp += d * d;
        }
    }

    // Phase 4: combined block reduction (4 doubles + 2 ints, 14 warps)
    double vals[4] = {(double)fdt, (double)fnx, (double)fny, (double)fpp};
    #pragma unroll
    for (int k = 0; k < 4; ++k) vals[k] = wredD(vals[k]);
    cx = wredI(cx);
    cy = wredI(cy);
    if (lane == 0) {
        #pragma unroll
        for (int k = 0; k < 4; ++k) redd[wid * 4 + k] = vals[k];
        redi[wid * 2 + 0] = cx;
        redi[wid * 2 + 1] = cy;
    }
    __syncthreads();                                   // B3

    if (tid == 0) {
        double dt = 0, nx = 0, ny = 0, pp = 0;
        int tcx = 0, tcy = 0;
        #pragma unroll
        for (int w = 0; w < NT / 32; ++w) {
            dt += redd[w * 4 + 0]; nx += redd[w * 4 + 1];
            ny += redd[w * 4 + 2]; pp += redd[w * 4 + 3];
            tcx += redi[w * 2 + 0]; tcy += redi[w * 2 + 1];
        }
        const double sd = nx - 2.0 * dt + ny;          // sum (a-b)^2
        const double mse_i = sd / (double)LEN;
        const double p2p_i = pp / (double)LEN;
        const double cosv  = dt / (sqrt(nx) * sqrt(ny));
        const double custom = (tcx != tcy) ? mse_i : 0.5 * p2p_i;  // ALPHA=1, BETA=0.5
        float4 r;
        r.x = (float)sd; r.y = (float)cosv; r.z = (float)pp; r.w = (float)custom;
        g_rowbuf[row] = r;
        __threadfence();
        s_isLast = (atomicAdd(&g_count, 1u) == BATCH - 1);
    }
    __syncthreads();                                   // B4

    // Phase 5: last block performs the deterministic final reduction
    if (s_isLast) {
        double s0 = 0, s1 = 0, s2 = 0, s3 = 0;
        for (int r = tid; r < BATCH; r += NT) {
            float4 p = g_rowbuf[r];
            s0 += (double)p.x; s1 += (double)p.y;
            s2 += (double)p.z; s3 += (double)p.w;
        }
        s0 = wredD(s0); s1 = wredD(s1); s2 = wredD(s2); s3 = wredD(s3);
        if (lane == 0) {
            redd[wid * 4 + 0] = s0; redd[wid * 4 + 1] = s1;
            redd[wid * 4 + 2] = s2; redd[wid * 4 + 3] = s3;
        }
        __syncthreads();
        if (tid == 0) {
            double t0 = 0, t1 = 0, t2 = 0, t3 = 0;
            #pragma unroll
            for (int w = 0; w < NT / 32; ++w) {
                t0 += redd[w * 4 + 0]; t1 += redd[w * 4 + 1];
                t2 += redd[w * 4 + 2]; t3 += redd[w * 4 + 3];
            }
            const double mse = t0 / ((double)BATCH * (double)LEN);
            out[0] = (float)(mse + t3);               // total_loss
            out[1] = (float)(t1 / (double)BATCH);     // cosine_similarity
            out[2] = (float)(t2 / (double)LEN);       // p2p_loss
            out[3] = (float)mse;                      // mse_loss
            g_count = 0;                              // reset for next replay
        }
    }
}

extern "C" void kernel_launch(void* const* d_in, const int* in_sizes, int n_in,
                              void* d_out, int out_size) {
    const float* x = (const float*)d_in[0];   // in_signal  [2048, 4096] f32
    const float* y = (const float*)d_in[1];   // ref_signal [2048, 4096] f32
    float* out = (float*)d_out;
    loss_kernel<<<BATCH, NT>>>(x, y, out);
}

// round 12
// speedup vs baseline: 1.2097x; 1.2097x over previous
#include <cuda_runtime.h>
#include <cstdint>
#include <math.h>

#define BATCH 2048
#define LEN   4096
#define NT    256
#define W     19
#define NBLK  218              // 218*19 = 4142 >= 20+4096+19
#define PRE   32               // front guard (-inf), covers reads down to p=-19
#define ASZ   4208             // PRE + 4142 + tail guard, 16B-aligned
#define DIDX  52               // smem index of signal element i=0 (p=20+i, +PRE)

__device__ float4   g_rowbuf[BATCH];
__device__ unsigned g_count;

// ---------------- cp.async helpers ----------------
__device__ __forceinline__ void cpAsync16(unsigned int saddr, const void* gptr) {
    asm volatile("cp.async.cg.shared.global [%0], [%1], 16;\n"
                 :: "r"(saddr), "l"(gptr));
}
__device__ __forceinline__ void cpCommit() {
    asm volatile("cp.async.commit_group;\n" ::);
}
template<int N> __device__ __forceinline__ void cpWait() {
    asm volatile("cp.async.wait_group %0;\n" :: "n"(N));
}

// ---------------- warp reductions ----------------
__device__ __forceinline__ double wredD(double v) {
    #pragma unroll
    for (int o = 16; o; o >>= 1) v += __shfl_down_sync(0xffffffffu, v, o);
    return v;
}
__device__ __forceinline__ int wredI(int v) {
    #pragma unroll
    for (int o = 16; o; o >>= 1) v += __shfl_down_sync(0xffffffffu, v, o);
    return v;
}

// ---------------- register-resident van Herk block, dense d10+d20 -----------
// Thread owns padded block [s, s+19). Full halo chains:
//   Sl[k] = max(B[k-19 .. -1]),  Pr[k] = max(B[19 .. 19+k])
// peak10: strict local max && v >= pooled19; peak20 = peak10 && v>=Sl[j]
// && v>=Pr[j] && v>=Mfull. -inf guards exclude pads; i=0 / i=LEN-1 false
// positives cleared by mask-bit at their owning (s, j) slots.
template<bool P2P>
__device__ __forceinline__ void processBlock(const float* __restrict__ A, int s,
                                             unsigned& mask, int& cnt20,
                                             const float* __restrict__ X,
                                             unsigned maskx, float& pp) {
    const float* B = A + PRE + s;    // B[j] = value at p = s+j

    float c[W];
    #pragma unroll
    for (int j = 0; j < W; ++j) c[j] = B[j];

    float Sl[W];                     // Sl[k] = max(B[k-19 .. -1])
    Sl[18] = B[-1];
    #pragma unroll
    for (int k = 17; k >= 0; --k) Sl[k] = fmaxf(B[k - 19], Sl[k + 1]);

    float Pr[W];                     // Pr[k] = max(B[19 .. 19+k])
    Pr[0] = B[W];
    #pragma unroll
    for (int k = 1; k < W; ++k) Pr[k] = fmaxf(Pr[k - 1], B[W + k]);

    // chain seeds double as Mfull parts (Mfull costs only 2 extra fmax)
    float maxL = c[0];
    #pragma unroll
    for (int k = 1; k < 9; ++k) maxL = fmaxf(maxL, c[k]);      // max(c[0..8])
    float maxR = c[18];
    #pragma unroll
    for (int k = 17; k >= 10; --k) maxR = fmaxf(maxR, c[k]);   // max(c[10..18])
    const float Mfull = fmaxf(fmaxf(maxL, maxR), c[9]);

    unsigned m10 = 0u, m20 = 0u;

    // ---- left: j = 0..8, pooled19 = max( Sl[j+10], c[0..j+9] )
    {
        float m = maxL;
        #pragma unroll
        for (int j = 0; j <= 8; ++j) {
            m = fmaxf(m, c[j + 9]);                            // max(c[0..j+9])
            const float v = c[j];
            const float left = (j == 0) ? Sl[18] : c[j - 1];
            const float nb = fmaxf(left, c[j + 1]);
            if (v > nb && v >= fmaxf(m, Sl[j + 10])) {
                m10 |= (1u << j);
                if (v >= Sl[j] && v >= Pr[j] && v >= Mfull) m20 |= (1u << j);
            }
        }
    }
    // ---- center: j = 9, pooled19 = Mfull
    {
        const float v = c[9];
        const float nb = fmaxf(c[8], c[10]);
        if (v > nb && v >= Mfull) {
            m10 |= (1u << 9);
            if (v >= Sl[9] && v >= Pr[9]) m20 |= (1u << 9);
        }
    }
    // ---- right: j = 18..10, pooled19 = max( c[j-9..18], Pr[j-10] )
    {
        float m = maxR;
        #pragma unroll
        for (int t = 9; t >= 1; --t) {
            const int j = t + 9;                               // 18..10
            m = fmaxf(m, c[t]);                                // max(c[t..18])
            const float v = c[j];
            const float right = (j == W - 1) ? Pr[0] : c[j + 1];
            const float nb = fmaxf(c[j - 1], right);
            if (v > nb && v >= fmaxf(m, Pr[t - 1])) {
                m10 |= (1u << j);
                if (v >= Sl[j] && v >= Pr[j] && v >= Mfull) m20 |= (1u << j);
            }
        }
    }

    // edge corrections: i=0 lives at (s=19, j=1); i=LEN-1 at (s=4104, j=11)
    if (s == 19)   { m10 &= ~(1u << 1);  m20 &= ~(1u << 1);  }
    if (s == 4104) { m10 &= ~(1u << 11); m20 &= ~(1u << 11); }

    mask = m10;
    cnt20 = __popc(m20);

    if (P2P) {  // sparse: nonzero terms only where either signal has a peak
        unsigned un = maskx | mask;
        while (un) {
            const int j = __ffs(un) - 1;
            un &= un - 1;
            const float pkx = ((maskx >> j) & 1u) ? X[PRE + s + j] : 0.f;
            const float pky = ((mask  >> j) & 1u) ? B[j] : 0.f;
            const float d = pkx - pky;
            pp += d * d;
        }
    }
}

// ---------------- main kernel ----------------
__global__ void __launch_bounds__(NT, 3)
loss_kernel(const float* __restrict__ xg, const float* __restrict__ yg,
            float* __restrict__ out) {
    __shared__ __align__(16) float xs[ASZ];
    __shared__ __align__(16) float ys[ASZ];
    __shared__ double redd[8 * 4];
    __shared__ int    redi[8 * 2];
    __shared__ int    s_isLast;

    const int tid  = threadIdx.x;
    const int lane = tid & 31;
    const int wid  = tid >> 5;
    const int row  = blockIdx.x;

    // Kick off async copies: x tile (group committed first), then y tile.
    const float4* x4 = (const float4*)(xg + (size_t)row * LEN);
    const float4* y4 = (const float4*)(yg + (size_t)row * LEN);
    const unsigned int xsm = (unsigned int)__cvta_generic_to_shared(xs + DIDX);
    const unsigned int ysm = (unsigned int)__cvta_generic_to_shared(ys + DIDX);
    #pragma unroll
    for (int k = 0; k < 4; ++k) {
        const int j = tid + k * NT;
        cpAsync16(xsm + j * 16, x4 + j);
    }
    cpCommit();
    #pragma unroll
    for (int k = 0; k < 4; ++k) {
        const int j = tid + k * NT;
        cpAsync16(ysm + j * 16, y4 + j);
    }
    cpCommit();

    // -inf guards while copies fly: idx [0,52) and [4148, 4208)  (112 slots)
    if (tid < 52 + (ASZ - 4148)) {
        const int idx = (tid < 52) ? tid : 4148 + (tid - 52);
        xs[idx] = -INFINITY;
        ys[idx] = -INFINITY;
    }

    cpWait<1>();                                       // own x copies done
    __syncthreads();                                   // B1: x resident

    // Phase 2a: process x blocks while y still streams in
    int cx = 0, cy = 0;
    unsigned mx = 0u, my;
    float fpp = 0.f;
    if (tid < NBLK) {
        processBlock<false>(xs, tid * W, mx, cx, ys, 0u, fpp);
    }

    cpWait<0>();                                       // own y copies done
    __syncthreads();                                   // B2: y resident

    // Phase 2b: elementwise partials from smem (conflict-free LDS.128)
    float fdt = 0.f, fnx = 0.f, fny = 0.f;
    {
        const float4* xs4 = (const float4*)(xs + DIDX);
        const float4* ys4 = (const float4*)(ys + DIDX);
        #pragma unroll
        for (int k = 0; k < 4; ++k) {
            const int j = tid + k * NT;
            float4 a = xs4[j], b = ys4[j];
            fdt += a.x*b.x + a.y*b.y + a.z*b.z + a.w*b.w;
            fnx += a.x*a.x + a.y*a.y + a.z*a.z + a.w*a.w;
            fny += b.x*b.x + b.y*b.y + b.z*b.z + b.w*b.w;
        }
    }

    // Phase 2c: process y blocks + fused sparse p2p against x mask
    if (tid < NBLK) {
        int c20;
        processBlock<true>(ys, tid * W, my, c20, xs, mx, fpp);
        cy = c20;
    }

    // Phase 3: combined block reduction (4 doubles + 2 ints)
    double vals[4] = {(double)fdt, (double)fnx, (double)fny, (double)fpp};
    #pragma unroll
    for (int k = 0; k < 4; ++k) vals[k] = wredD(vals[k]);
    cx = wredI(cx);
    cy = wredI(cy);
    if (lane == 0) {
        #pragma unroll
        for (int k = 0; k < 4; ++k) redd[wid * 4 + k] = vals[k];
        redi[wid * 2 + 0] = cx;
        redi[wid * 2 + 1] = cy;
    }
    __syncthreads();                                   // B3

    if (tid == 0) {
        double dt = 0, nx = 0, ny = 0, pp = 0;
        int tcx = 0, tcy = 0;
        #pragma unroll
        for (int w = 0; w < NT / 32; ++w) {
            dt += redd[w * 4 + 0]; nx += redd[w * 4 + 1];
            ny += redd[w * 4 + 2]; pp += redd[w * 4 + 3];
            tcx += redi[w * 2 + 0]; tcy += redi[w * 2 + 1];
        }
        const double sd = nx - 2.0 * dt + ny;          // sum (a-b)^2
        const double mse_i = sd / (double)LEN;
        const double p2p_i = pp / (double)LEN;
        const double cosv  = dt / (sqrt(nx) * sqrt(ny));
        const double custom = (tcx != tcy) ? mse_i : 0.5 * p2p_i;  // ALPHA=1, BETA=0.5
        float4 r;
        r.x = (float)sd; r.y = (float)cosv; r.z = (float)pp; r.w = (float)custom;
        g_rowbuf[row] = r;
        __threadfence();
        s_isLast = (atomicAdd(&g_count, 1u) == BATCH - 1);
    }
    __syncthreads();                                   // B4

    // Phase 4: last block performs the deterministic final reduction
    if (s_isLast) {
        double s0 = 0, s1 = 0, s2 = 0, s3 = 0;
        for (int r = tid; r < BATCH; r += NT) {
            float4 p = g_rowbuf[r];
            s0 += (double)p.x; s1 += (double)p.y;
            s2 += (double)p.z; s3 += (double)p.w;
        }
        s0 = wredD(s0); s1 = wredD(s1); s2 = wredD(s2); s3 = wredD(s3);
        if (lane == 0) {
            redd[wid * 4 + 0] = s0; redd[wid * 4 + 1] = s1;
            redd[wid * 4 + 2] = s2; redd[wid * 4 + 3] = s3;
        }
        __syncthreads();
        if (tid == 0) {
            double t0 = 0, t1 = 0, t2 = 0, t3 = 0;
            #pragma unroll
            for (int w = 0; w < NT / 32; ++w) {
                t0 += redd[w * 4 + 0]; t1 += redd[w * 4 + 1];
                t2 += redd[w * 4 + 2]; t3 += redd[w * 4 + 3];
            }
            const double mse = t0 / ((double)BATCH * (double)LEN);
            out[0] = (float)(mse + t3);               // total_loss
            out[1] = (float)(t1 / (double)BATCH);     // cosine_similarity
            out[2] = (float)(t2 / (double)LEN);       // p2p_loss
            out[3] = (float)mse;                      // mse_loss
            g_count = 0;                              // reset for next replay
        }
    }
}

extern "C" void kernel_launch(void* const* d_in, const int* in_sizes, int n_in,
                              void* d_out, int out_size) {
    const float* x = (const float*)d_in[0];   // in_signal  [2048, 4096] f32
    const float* y = (const float*)d_in[1];   // ref_signal [2048, 4096] f32
    float* out = (float*)d_out;
    loss_kernel<<<BATCH, NT>>>(x, y, out);
}

// round 13
// speedup vs baseline: 1.3099x; 1.0828x over previous
#include <cuda_runtime.h>
#include <cstdint>
#include <math.h>

#define BATCH 2048
#define LEN   4096
#define NT    448              // two 224-thread halves, one row each
#define HT    224
#define W     19
#define NBLK  218              // 218*19 = 4142 >= 20+4096+19
#define PRE   32               // front guard (-inf), covers reads down to p=-19
#define ASZ   4208             // PRE + 4142 + tail guard, 16B-aligned
#define DIDX  52               // smem index of signal element i=0 (p=20+i, +PRE)

// dynamic smem layout (floats): xsA ysA xsB ysB | redd(14*4 dbl) redi(14*2 int)
#define SM_RED_OFF   (4 * ASZ * 4)                 // byte offset of redd
#define SM_REDI_OFF  (SM_RED_OFF + 14 * 4 * 8)
#define SMEM_BYTES   (SM_REDI_OFF + 14 * 2 * 4 + 16)

__device__ float4   g_rowbuf[BATCH];
__device__ unsigned g_count;

// ---------------- warp reductions ----------------
__device__ __forceinline__ double wredD(double v) {
    #pragma unroll
    for (int o = 16; o; o >>= 1) v += __shfl_down_sync(0xffffffffu, v, o);
    return v;
}
__device__ __forceinline__ int wredI(int v) {
    #pragma unroll
    for (int o = 16; o; o >>= 1) v += __shfl_down_sync(0xffffffffu, v, o);
    return v;
}

// ---------------- register-resident van Herk block, dense d10+d20 -----------
// Thread owns padded block [s, s+19). Full halo chains:
//   Sl[k] = max(B[k-19 .. -1]),  Pr[k] = max(B[19 .. 19+k])
// peak10: strict local max && v >= pooled19.
// peak20 = peak10 && v >= max(Sl[j], Pr[j], Mfull)  (full +/-19 window).
// -inf guards exclude pads; i=0 / i=LEN-1 false positives cleared by
// mask-bit at their owning (s, j) slots.
template<bool P2P>
__device__ __forceinline__ void processBlock(const float* __restrict__ A, int s,
                                             unsigned& mask, int& cnt20,
                                             const float* __restrict__ X,
                                             unsigned maskx, float& pp) {
    const float* B = A + PRE + s;    // B[j] = value at p = s+j

    float c[W];
    #pragma unroll
    for (int j = 0; j < W; ++j) c[j] = B[j];

    float Sl[W];                     // Sl[k] = max(B[k-19 .. -1])
    Sl[18] = B[-1];
    #pragma unroll
    for (int k = 17; k >= 0; --k) Sl[k] = fmaxf(B[k - 19], Sl[k + 1]);

    float Pr[W];                     // Pr[k] = max(B[19 .. 19+k])
    Pr[0] = B[W];
    #pragma unroll
    for (int k = 1; k < W; ++k) Pr[k] = fmaxf(Pr[k - 1], B[W + k]);

    // chain seeds double as Mfull parts (Mfull costs only 2 extra fmax)
    float maxL = c[0];
    #pragma unroll
    for (int k = 1; k < 9; ++k) maxL = fmaxf(maxL, c[k]);      // max(c[0..8])
    float maxR = c[18];
    #pragma unroll
    for (int k = 17; k >= 10; --k) maxR = fmaxf(maxR, c[k]);   // max(c[10..18])
    const float Mfull = fmaxf(fmaxf(maxL, maxR), c[9]);

    unsigned m10 = 0u, m20 = 0u;

    // ---- left: j = 0..8, pooled19 = max( Sl[j+10], c[0..j+9] )
    {
        float m = maxL;
        #pragma unroll
        for (int j = 0; j <= 8; ++j) {
            m = fmaxf(m, c[j + 9]);                            // max(c[0..j+9])
            const float v = c[j];
            const float left = (j == 0) ? Sl[18] : c[j - 1];
            const float nb = fmaxf(left, c[j + 1]);
            if (v > nb && v >= fmaxf(m, Sl[j + 10])) {
                m10 |= (1u << j);
                if (v >= fmaxf(fmaxf(Sl[j], Pr[j]), Mfull)) m20 |= (1u << j);
            }
        }
    }
    // ---- center: j = 9, pooled19 = Mfull
    {
        const float v = c[9];
        const float nb = fmaxf(c[8], c[10]);
        if (v > nb && v >= Mfull) {
            m10 |= (1u << 9);
            if (v >= fmaxf(Sl[9], Pr[9])) m20 |= (1u << 9);
        }
    }
    // ---- right: j = 18..10, pooled19 = max( c[j-9..18], Pr[j-10] )
    {
        float m = maxR;
        #pragma unroll
        for (int t = 9; t >= 1; --t) {
            const int j = t + 9;                               // 18..10
            m = fmaxf(m, c[t]);                                // max(c[t..18])
            const float v = c[j];
            const float right = (j == W - 1) ? Pr[0] : c[j + 1];
            const float nb = fmaxf(c[j - 1], right);
            if (v > nb && v >= fmaxf(m, Pr[t - 1])) {
                m10 |= (1u << j);
                if (v >= fmaxf(fmaxf(Sl[j], Pr[j]), Mfull)) m20 |= (1u << j);
            }
        }
    }

    // edge corrections: i=0 lives at (s=19, j=1); i=LEN-1 at (s=4104, j=11)
    if (s == 19)   { m10 &= ~(1u << 1);  m20 &= ~(1u << 1);  }
    if (s == 4104) { m10 &= ~(1u << 11); m20 &= ~(1u << 11); }

    mask = m10;
    cnt20 = __popc(m20);

    if (P2P) {  // sparse: nonzero terms only where either signal has a peak
        unsigned un = maskx | mask;
        while (un) {
            const int j = __ffs(un) - 1;
            un &= un - 1;
            const float pkx = ((maskx >> j) & 1u) ? X[PRE + s + j] : 0.f;
            const float pky = ((mask  >> j) & 1u) ? B[j] : 0.f;
            const float d = pkx - pky;
            pp += d * d;
        }
    }
}

// ---------------- main kernel: 2 rows per CTA, independent halves -----------
__global__ void __launch_bounds__(NT, 2)
loss_kernel(const float* __restrict__ xg, const float* __restrict__ yg,
            float* __restrict__ out) {
    extern __shared__ __align__(16) char smraw[];
    __shared__ int s_isLast;

    const int tid  = threadIdx.x;
    const int lane = tid & 31;
    const int wid  = tid >> 5;              // warps 0-6: half A, 7-13: half B
    const int half = (tid >= HT);
    const int t2   = tid - half * HT;       // 0..223 within the half
    const int row  = blockIdx.x * 2 + half;

    float* xs = (float*)smraw + half * (2 * ASZ);
    float* ys = xs + ASZ;
    double* redd = (double*)(smraw + SM_RED_OFF);   // 14 warps * 4
    int*    redi = (int*)(smraw + SM_REDI_OFF);     // 14 warps * 2

    // -inf guards: idx [0,52) and [4148, 4208)  (112 slots per half)
    if (t2 < 52 + (ASZ - 4148)) {
        const int idx = (t2 < 52) ? t2 : 4148 + (t2 - 52);
        xs[idx] = -INFINITY;
        ys[idx] = -INFINITY;
    }

    // Phase 1: coalesced load + fp32 elementwise partials (dot + norms only;
    // sum of squared diffs recovered as nx - 2*dt + ny in fp64 at combine).
    // 1024 float4 per signal over 224 threads: warps 0-3 run 5 iters, 4-6 run 4.
    const float4* x4 = (const float4*)(xg + (size_t)row * LEN);
    const float4* y4 = (const float4*)(yg + (size_t)row * LEN);
    float4* xs4 = (float4*)(xs + DIDX);
    float4* ys4 = (float4*)(ys + DIDX);
    float fdt = 0.f, fnx = 0.f, fny = 0.f;
    for (int j = t2; j < LEN / 4; j += HT) {
        float4 a = x4[j], b = y4[j];
        xs4[j] = a; ys4[j] = b;
        fdt += a.x*b.x + a.y*b.y + a.z*b.z + a.w*b.w;
        fnx += a.x*a.x + a.y*a.y + a.z*a.z + a.w*a.w;
        fny += b.x*b.x + b.y*b.y + b.z*b.z + b.w*b.w;
    }
    __syncthreads();                                   // B1: rows resident

    // Phase 2: per-thread block processing, x then y (no inter-half deps)
    int cx = 0, cy = 0;
    float fpp = 0.f;
    if (t2 < NBLK) {
        const int s = t2 * W;
        unsigned mx, my;
        int c20;
        processBlock<false>(xs, s, mx, c20, ys, 0u, fpp);
        cx = c20;
        processBlock<true>(ys, s, my, c20, xs, mx, fpp);
        cy = c20;
    }

    // Phase 3: warp reductions (warps are half-pure: boundary at warp 7)
    double vals[4] = {(double)fdt, (double)fnx, (double)fny, (double)fpp};
    #pragma unroll
    for (int k = 0; k < 4; ++k) vals[k] = wredD(vals[k]);
    cx = wredI(cx);
    cy = wredI(cy);
    if (lane == 0) {
        #pragma unroll
        for (int k = 0; k < 4; ++k) redd[wid * 4 + k] = vals[k];
        redi[wid * 2 + 0] = cx;
        redi[wid * 2 + 1] = cy;
    }
    __syncthreads();                                   // B2

    // tid 0 combines BOTH rows (single-writer for fence/atomic correctness)
    if (tid == 0) {
        #pragma unroll
        for (int h = 0; h < 2; ++h) {
            double dt = 0, nx = 0, ny = 0, pp = 0;
            int tcx = 0, tcy = 0;
            #pragma unroll
            for (int w = h * 7; w < h * 7 + 7; ++w) {
                dt += redd[w * 4 + 0]; nx += redd[w * 4 + 1];
                ny += redd[w * 4 + 2]; pp += redd[w * 4 + 3];
                tcx += redi[w * 2 + 0]; tcy += redi[w * 2 + 1];
            }
            const double sd = nx - 2.0 * dt + ny;      // sum (a-b)^2
            const double mse_i = sd / (double)LEN;
            const double p2p_i = pp / (double)LEN;
            const double cosv  = dt / (sqrt(nx) * sqrt(ny));
            const double custom = (tcx != tcy) ? mse_i : 0.5 * p2p_i; // A=1,B=.5
            float4 r;
            r.x = (float)sd; r.y = (float)cosv; r.z = (float)pp; r.w = (float)custom;
            g_rowbuf[blockIdx.x * 2 + h] = r;
        }
        __threadfence();
        s_isLast = (atomicAdd(&g_count, 1u) == (BATCH / 2) - 1);
    }
    __syncthreads();                                   // B3

    // Phase 4: last CTA performs the deterministic final reduction
    if (s_isLast) {
        double s0 = 0, s1 = 0, s2 = 0, s3 = 0;
        for (int r = tid; r < BATCH; r += NT) {
            float4 p = g_rowbuf[r];
            s0 += (double)p.x; s1 += (double)p.y;
            s2 += (double)p.z; s3 += (double)p.w;
        }
        s0 = wredD(s0); s1 = wredD(s1); s2 = wredD(s2); s3 = wredD(s3);
        if (lane == 0) {
            redd[wid * 4 + 0] = s0; redd[wid * 4 + 1] = s1;
            redd[wid * 4 + 2] = s2; redd[wid * 4 + 3] = s3;
        }
        __syncthreads();
        if (tid == 0) {
            double t0 = 0, t1 = 0, t2s = 0, t3 = 0;
            #pragma unroll
            for (int w = 0; w < NT / 32; ++w) {
                t0 += redd[w * 4 + 0]; t1 += redd[w * 4 + 1];
                t2s += redd[w * 4 + 2]; t3 += redd[w * 4 + 3];
            }
            const double mse = t0 / ((double)BATCH * (double)LEN);
            out[0] = (float)(mse + t3);               // total_loss
            out[1] = (float)(t1 / (double)BATCH);     // cosine_similarity
            out[2] = (float)(t2s / (double)LEN);      // p2p_loss
            out[3] = (float)mse;                      // mse_loss
            g_count = 0;                              // reset for next replay
        }
    }
}

extern "C" void kernel_launch(void* const* d_in, const int* in_sizes, int n_in,
                              void* d_out, int out_size) {
    const float* x = (const float*)d_in[0];   // in_signal  [2048, 4096] f32
    const float* y = (const float*)d_in[1];   // ref_signal [2048, 4096] f32
    float* out = (float*)d_out;

    cudaFuncSetAttribute(loss_kernel,
                         cudaFuncAttributeMaxDynamicSharedMemorySize, SMEM_BYTES);
    loss_kernel<<<BATCH / 2, NT, SMEM_BYTES>>>(x, y, out);
}

// round 14
// speedup vs baseline: 1.3686x; 1.0448x over previous
#include <cuda_runtime.h>
#include <cstdint>
#include <math.h>

#define BATCH 2048
#define LEN   4096
#define NT    448              // two 224-thread halves, one row each
#define HT    224
#define W     19
#define NBLK  218              // 218*19 = 4142 >= 20+4096+19
#define PRE   32               // front guard (-inf), covers reads down to p=-19
#define ASZ   4208             // PRE + 4142 + tail guard, 16B-aligned
#define DIDX  52               // smem index of signal element i=0 (p=20+i, +PRE)

// dynamic smem layout (floats): xsA ysA xsB ysB | redd(14*4 dbl) redi(14*2 int)
#define SM_RED_OFF   (4 * ASZ * 4)                 // byte offset of redd
#define SM_REDI_OFF  (SM_RED_OFF + 14 * 4 * 8)
#define SMEM_BYTES   (SM_REDI_OFF + 14 * 2 * 4 + 16)

__device__ float4   g_rowbuf[BATCH];
__device__ unsigned g_count;

// ---------------- warp reductions ----------------
__device__ __forceinline__ double wredD(double v) {
    #pragma unroll
    for (int o = 16; o; o >>= 1) v += __shfl_down_sync(0xffffffffu, v, o);
    return v;
}
__device__ __forceinline__ int wredI(int v) {
    #pragma unroll
    for (int o = 16; o; o >>= 1) v += __shfl_down_sync(0xffffffffu, v, o);
    return v;
}

// ---------------- register-resident van Herk block, dense d10+d20 -----------
// Thread owns padded block [s, s+19). Full halo chains:
//   Sl[k] = max(B[k-19 .. -1]),  Pr[k] = max(B[19 .. 19+k])
// peak10: strict local max && v >= pooled19.
// peak20 = peak10 && v >= max(Sl[j], Pr[j], Mfull)  (full +/-19 window).
// -inf guards exclude pads; i=0 / i=LEN-1 false positives cleared by
// mask-bit at their owning (s, j) slots.
template<bool P2P>
__device__ __forceinline__ void processBlock(const float* __restrict__ A, int s,
                                             unsigned& mask, int& cnt20,
                                             const float* __restrict__ X,
                                             unsigned maskx, float& pp) {
    const float* B = A + PRE + s;    // B[j] = value at p = s+j

    float c[W];
    #pragma unroll
    for (int j = 0; j < W; ++j) c[j] = B[j];

    float Sl[W];                     // Sl[k] = max(B[k-19 .. -1])
    Sl[18] = B[-1];
    #pragma unroll
    for (int k = 17; k >= 0; --k) Sl[k] = fmaxf(B[k - 19], Sl[k + 1]);

    float Pr[W];                     // Pr[k] = max(B[19 .. 19+k])
    Pr[0] = B[W];
    #pragma unroll
    for (int k = 1; k < W; ++k) Pr[k] = fmaxf(Pr[k - 1], B[W + k]);

    // chain seeds double as Mfull parts (Mfull costs only 2 extra fmax)
    float maxL = c[0];
    #pragma unroll
    for (int k = 1; k < 9; ++k) maxL = fmaxf(maxL, c[k]);      // max(c[0..8])
    float maxR = c[18];
    #pragma unroll
    for (int k = 17; k >= 10; --k) maxR = fmaxf(maxR, c[k]);   // max(c[10..18])
    const float Mfull = fmaxf(fmaxf(maxL, maxR), c[9]);

    unsigned m10 = 0u, m20 = 0u;

    // ---- left: j = 0..8, pooled19 = max( Sl[j+10], c[0..j+9] )
    {
        float m = maxL;
        #pragma unroll
        for (int j = 0; j <= 8; ++j) {
            m = fmaxf(m, c[j + 9]);                            // max(c[0..j+9])
            const float v = c[j];
            const float left = (j == 0) ? Sl[18] : c[j - 1];
            const float nb = fmaxf(left, c[j + 1]);
            if (v > nb && v >= fmaxf(m, Sl[j + 10])) {
                m10 |= (1u << j);
                if (v >= fmaxf(fmaxf(Sl[j], Pr[j]), Mfull)) m20 |= (1u << j);
            }
        }
    }
    // ---- center: j = 9, pooled19 = Mfull
    {
        const float v = c[9];
        const float nb = fmaxf(c[8], c[10]);
        if (v > nb && v >= Mfull) {
            m10 |= (1u << 9);
            if (v >= fmaxf(Sl[9], Pr[9])) m20 |= (1u << 9);
        }
    }
    // ---- right: j = 18..10, pooled19 = max( c[j-9..18], Pr[j-10] )
    {
        float m = maxR;
        #pragma unroll
        for (int t = 9; t >= 1; --t) {
            const int j = t + 9;                               // 18..10
            m = fmaxf(m, c[t]);                                // max(c[t..18])
            const float v = c[j];
            const float right = (j == W - 1) ? Pr[0] : c[j + 1];
            const float nb = fmaxf(c[j - 1], right);
            if (v > nb && v >= fmaxf(m, Pr[t - 1])) {
                m10 |= (1u << j);
                if (v >= fmaxf(fmaxf(Sl[j], Pr[j]), Mfull)) m20 |= (1u << j);
            }
        }
    }

    // edge corrections: i=0 lives at (s=19, j=1); i=LEN-1 at (s=4104, j=11)
    if (s == 19)   { m10 &= ~(1u << 1);  m20 &= ~(1u << 1);  }
    if (s == 4104) { m10 &= ~(1u << 11); m20 &= ~(1u << 11); }

    mask = m10;
    cnt20 = __popc(m20);

    if (P2P) {  // sparse: nonzero terms only where either signal has a peak
        unsigned un = maskx | mask;
        while (un) {
            const int j = __ffs(un) - 1;
            un &= un - 1;
            const float pkx = ((maskx >> j) & 1u) ? X[PRE + s + j] : 0.f;
            const float pky = ((mask  >> j) & 1u) ? B[j] : 0.f;
            const float d = pkx - pky;
            pp += d * d;
        }
    }
}

// ---------------- main kernel: 2 rows per CTA, independent halves -----------
__global__ void __launch_bounds__(NT, 2)
loss_kernel(const float* __restrict__ xg, const float* __restrict__ yg,
            float* __restrict__ out) {
    extern __shared__ __align__(16) char smraw[];
    __shared__ int s_isLast;

    const int tid  = threadIdx.x;
    const int lane = tid & 31;
    const int wid  = tid >> 5;              // warps 0-6: half A, 7-13: half B
    const int half = (tid >= HT);
    const int t2   = tid - half * HT;       // 0..223 within the half
    const int row  = blockIdx.x * 2 + half;

    float* xs = (float*)smraw + half * (2 * ASZ);
    float* ys = xs + ASZ;
    double* redd = (double*)(smraw + SM_RED_OFF);   // 14 warps * 4
    int*    redi = (int*)(smraw + SM_REDI_OFF);     // 14 warps * 2

    // -inf guards: idx [0,52) and [4148, 4208)  (112 slots per half)
    if (t2 < 52 + (ASZ - 4148)) {
        const int idx = (t2 < 52) ? t2 : 4148 + (t2 - 52);
        xs[idx] = -INFINITY;
        ys[idx] = -INFINITY;
    }

    // Phase 1: coalesced load + fp32 elementwise partials (dot + norms only;
    // sum of squared diffs recovered as nx - 2*dt + ny in fp64 at combine).
    // Compile-time unrolled (5 iters, last predicated) so ptxas batches the
    // LDG.128s for high MLP instead of a serial dynamic-trip loop.
    const float4* x4 = (const float4*)(xg + (size_t)row * LEN);
    const float4* y4 = (const float4*)(yg + (size_t)row * LEN);
    float4* xs4 = (float4*)(xs + DIDX);
    float4* ys4 = (float4*)(ys + DIDX);
    float fdt = 0.f, fnx = 0.f, fny = 0.f;
    #pragma unroll
    for (int k = 0; k < 5; ++k) {
        const int j = t2 + k * HT;
        if (k < 4 || j < LEN / 4) {
            float4 a = x4[j], b = y4[j];
            xs4[j] = a; ys4[j] = b;
            fdt += a.x*b.x + a.y*b.y + a.z*b.z + a.w*b.w;
            fnx += a.x*a.x + a.y*a.y + a.z*a.z + a.w*a.w;
            fny += b.x*b.x + b.y*b.y + b.z*b.z + b.w*b.w;
        }
    }
    __syncthreads();                                   // B1: rows resident

    // Phase 2: per-thread block processing, x then y (no inter-half deps)
    int cx = 0, cy = 0;
    float fpp = 0.f;
    if (t2 < NBLK) {
        const int s = t2 * W;
        unsigned mx, my;
        int c20;
        processBlock<false>(xs, s, mx, c20, ys, 0u, fpp);
        cx = c20;
        processBlock<true>(ys, s, my, c20, xs, mx, fpp);
        cy = c20;
    }

    // Phase 3: warp reductions (warps are half-pure: boundary at warp 7)
    double vals[4] = {(double)fdt, (double)fnx, (double)fny, (double)fpp};
    #pragma unroll
    for (int k = 0; k < 4; ++k) vals[k] = wredD(vals[k]);
    cx = wredI(cx);
    cy = wredI(cy);
    if (lane == 0) {
        #pragma unroll
        for (int k = 0; k < 4; ++k) redd[wid * 4 + k] = vals[k];
        redi[wid * 2 + 0] = cx;
        redi[wid * 2 + 1] = cy;
    }
    __syncthreads();                                   // B2

    // tid 0 combines BOTH rows (single-writer for fence/atomic correctness)
    if (tid == 0) {
        #pragma unroll
        for (int h = 0; h < 2; ++h) {
            double dt = 0, nx = 0, ny = 0, pp = 0;
            int tcx = 0, tcy = 0;
            #pragma unroll
            for (int w = h * 7; w < h * 7 + 7; ++w) {
                dt += redd[w * 4 + 0]; nx += redd[w * 4 + 1];
                ny += redd[w * 4 + 2]; pp += redd[w * 4 + 3];
                tcx += redi[w * 2 + 0]; tcy += redi[w * 2 + 1];
            }
            const double sd = nx - 2.0 * dt + ny;      // sum (a-b)^2
            const double mse_i = sd / (double)LEN;
            const double p2p_i = pp / (double)LEN;
            const double cosv  = dt / (sqrt(nx) * sqrt(ny));
            const double custom = (tcx != tcy) ? mse_i : 0.5 * p2p_i; // A=1,B=.5
            float4 r;
            r.x = (float)sd; r.y = (float)cosv; r.z = (float)pp; r.w = (float)custom;
            g_rowbuf[blockIdx.x * 2 + h] = r;
        }
        __threadfence();
        s_isLast = (atomicAdd(&g_count, 1u) == (BATCH / 2) - 1);
    }
    __syncthreads();                                   // B3

    // Phase 4: last CTA performs the deterministic final reduction
    if (s_isLast) {
        double s0 = 0, s1 = 0, s2 = 0, s3 = 0;
        for (int r = tid; r < BATCH; r += NT) {
            float4 p = g_rowbuf[r];
            s0 += (double)p.x; s1 += (double)p.y;
            s2 += (double)p.z; s3 += (double)p.w;
        }
        s0 = wredD(s0); s1 = wredD(s1); s2 = wredD(s2); s3 = wredD(s3);
        if (lane == 0) {
            redd[wid * 4 + 0] = s0; redd[wid * 4 + 1] = s1;
            redd[wid * 4 + 2] = s2; redd[wid * 4 + 3] = s3;
        }
        __syncthreads();
        if (tid == 0) {
            double t0 = 0, t1 = 0, t2s = 0, t3 = 0;
            #pragma unroll
            for (int w = 0; w < NT / 32; ++w) {
                t0 += redd[w * 4 + 0]; t1 += redd[w * 4 + 1];
                t2s += redd[w * 4 + 2]; t3 += redd[w * 4 + 3];
            }
            const double mse = t0 / ((double)BATCH * (double)LEN);
            out[0] = (float)(mse + t3);               // total_loss
            out[1] = (float)(t1 / (double)BATCH);     // cosine_similarity
            out[2] = (float)(t2s / (double)LEN);      // p2p_loss
            out[3] = (float)mse;                      // mse_loss
            g_count = 0;                              // reset for next replay
        }
    }
}

extern "C" void kernel_launch(void* const* d_in, const int* in_sizes, int n_in,
                              void* d_out, int out_size) {
    const float* x = (const float*)d_in[0];   // in_signal  [2048, 4096] f32
    const float* y = (const float*)d_in[1];   // ref_signal [2048, 4096] f32
    float* out = (float*)d_out;

    cudaFuncSetAttribute(loss_kernel,
                         cudaFuncAttributeMaxDynamicSharedMemorySize, SMEM_BYTES);
    loss_kernel<<<BATCH / 2, NT, SMEM_BYTES>>>(x, y, out);
}

// round 15
// speedup vs baseline: 1.4000x; 1.0229x over previous
#include <cuda_runtime.h>
#include <cstdint>
#include <math.h>

#define BATCH 2048
#define LEN   4096
#define NT    224              // one row per 224-thread CTA, 7 warps
#define W     19
#define NBLK  218              // 218*19 = 4142 >= 20+4096+19
#define PRE   32               // front guard (-inf), covers reads down to p=-19
#define ASZ   4208             // PRE + 4142 + tail guard, 16B-aligned
#define DIDX  52               // smem index of signal element i=0 (p=20+i, +PRE)

__device__ float4   g_rowbuf[BATCH];
__device__ unsigned g_count;

// ---------------- warp reductions ----------------
__device__ __forceinline__ double wredD(double v) {
    #pragma unroll
    for (int o = 16; o; o >>= 1) v += __shfl_down_sync(0xffffffffu, v, o);
    return v;
}
__device__ __forceinline__ int wredI(int v) {
    #pragma unroll
    for (int o = 16; o; o >>= 1) v += __shfl_down_sync(0xffffffffu, v, o);
    return v;
}

// ---------------- register-resident van Herk block, dense d10+d20 -----------
// Thread owns padded block [s, s+19). Full halo chains:
//   Sl[k] = max(B[k-19 .. -1]),  Pr[k] = max(B[19 .. 19+k])
// peak10: strict local max && v >= pooled19.
// peak20 = peak10 && v >= max(Sl[j], Pr[j], Mfull)  (full +/-19 window).
// -inf guards exclude pads; i=0 / i=LEN-1 false positives cleared by
// mask-bit at their owning (s, j) slots.
template<bool P2P>
__device__ __forceinline__ void processBlock(const float* __restrict__ A, int s,
                                             unsigned& mask, int& cnt20,
                                             const float* __restrict__ X,
                                             unsigned maskx, float& pp) {
    const float* B = A + PRE + s;    // B[j] = value at p = s+j

    float c[W];
    #pragma unroll
    for (int j = 0; j < W; ++j) c[j] = B[j];

    float Sl[W];                     // Sl[k] = max(B[k-19 .. -1])
    Sl[18] = B[-1];
    #pragma unroll
    for (int k = 17; k >= 0; --k) Sl[k] = fmaxf(B[k - 19], Sl[k + 1]);

    float Pr[W];                     // Pr[k] = max(B[19 .. 19+k])
    Pr[0] = B[W];
    #pragma unroll
    for (int k = 1; k < W; ++k) Pr[k] = fmaxf(Pr[k - 1], B[W + k]);

    // chain seeds double as Mfull parts (Mfull costs only 2 extra fmax)
    float maxL = c[0];
    #pragma unroll
    for (int k = 1; k < 9; ++k) maxL = fmaxf(maxL, c[k]);      // max(c[0..8])
    float maxR = c[18];
    #pragma unroll
    for (int k = 17; k >= 10; --k) maxR = fmaxf(maxR, c[k]);   // max(c[10..18])
    const float Mfull = fmaxf(fmaxf(maxL, maxR), c[9]);

    unsigned m10 = 0u, m20 = 0u;

    // ---- left: j = 0..8, pooled19 = max( Sl[j+10], c[0..j+9] )
    {
        float m = maxL;
        #pragma unroll
        for (int j = 0; j <= 8; ++j) {
            m = fmaxf(m, c[j + 9]);                            // max(c[0..j+9])
            const float v = c[j];
            const float left = (j == 0) ? Sl[18] : c[j - 1];
            const float nb = fmaxf(left, c[j + 1]);
            if (v > nb && v >= fmaxf(m, Sl[j + 10])) {
                m10 |= (1u << j);
                if (v >= fmaxf(fmaxf(Sl[j], Pr[j]), Mfull)) m20 |= (1u << j);
            }
        }
    }
    // ---- center: j = 9, pooled19 = Mfull
    {
        const float v = c[9];
        const float nb = fmaxf(c[8], c[10]);
        if (v > nb && v >= Mfull) {
            m10 |= (1u << 9);
            if (v >= fmaxf(Sl[9], Pr[9])) m20 |= (1u << 9);
        }
    }
    // ---- right: j = 18..10, pooled19 = max( c[j-9..18], Pr[j-10] )
    {
        float m = maxR;
        #pragma unroll
        for (int t = 9; t >= 1; --t) {
            const int j = t + 9;                               // 18..10
            m = fmaxf(m, c[t]);                                // max(c[t..18])
            const float v = c[j];
            const float right = (j == W - 1) ? Pr[0] : c[j + 1];
            const float nb = fmaxf(c[j - 1], right);
            if (v > nb && v >= fmaxf(m, Pr[t - 1])) {
                m10 |= (1u << j);
                if (v >= fmaxf(fmaxf(Sl[j], Pr[j]), Mfull)) m20 |= (1u << j);
            }
        }
    }

    // edge corrections: i=0 lives at (s=19, j=1); i=LEN-1 at (s=4104, j=11)
    if (s == 19)   { m10 &= ~(1u << 1);  m20 &= ~(1u << 1);  }
    if (s == 4104) { m10 &= ~(1u << 11); m20 &= ~(1u << 11); }

    mask = m10;
    cnt20 = __popc(m20);

    if (P2P) {  // sparse: nonzero terms only where either signal has a peak
        unsigned un = maskx | mask;
        while (un) {
            const int j = __ffs(un) - 1;
            un &= un - 1;
            const float pkx = ((maskx >> j) & 1u) ? X[PRE + s + j] : 0.f;
            const float pky = ((mask  >> j) & 1u) ? B[j] : 0.f;
            const float d = pkx - pky;
            pp += d * d;
        }
    }
}

// ---------------- main kernel: 1 row per 224-thread CTA ----------------
__global__ void __launch_bounds__(NT, 4)
loss_kernel(const float* __restrict__ xg, const float* __restrict__ yg,
            float* __restrict__ out) {
    __shared__ __align__(16) float xs[ASZ];
    __shared__ __align__(16) float ys[ASZ];
    __shared__ double redd[7 * 4];
    __shared__ int    redi[7 * 2];
    __shared__ int    s_isLast;

    const int tid  = threadIdx.x;
    const int lane = tid & 31;
    const int wid  = tid >> 5;
    const int row  = blockIdx.x;

    // -inf guards: idx [0,52) and [4148, 4208)  (112 slots, one shot at NT=224)
    if (tid < 52 + (ASZ - 4148)) {
        const int idx = (tid < 52) ? tid : 4148 + (tid - 52);
        xs[idx] = -INFINITY;
        ys[idx] = -INFINITY;
    }

    // Phase 1: coalesced load + fp32 elementwise partials (dot + norms only;
    // sum of squared diffs recovered as nx - 2*dt + ny in fp64 at combine).
    // Compile-time unrolled (5 iters, last predicated) so ptxas batches the
    // LDG.128s for high MLP.
    const float4* x4 = (const float4*)(xg + (size_t)row * LEN);
    const float4* y4 = (const float4*)(yg + (size_t)row * LEN);
    float4* xs4 = (float4*)(xs + DIDX);
    float4* ys4 = (float4*)(ys + DIDX);
    float fdt = 0.f, fnx = 0.f, fny = 0.f;
    #pragma unroll
    for (int k = 0; k < 5; ++k) {
        const int j = tid + k * NT;
        if (k < 4 || j < LEN / 4) {
            float4 a = x4[j], b = y4[j];
            xs4[j] = a; ys4[j] = b;
            fdt += a.x*b.x + a.y*b.y + a.z*b.z + a.w*b.w;
            fnx += a.x*a.x + a.y*a.y + a.z*a.z + a.w*a.w;
            fny += b.x*b.x + b.y*b.y + b.z*b.z + b.w*b.w;
        }
    }
    __syncthreads();                                   // B1: row resident

    // Phase 2: per-thread block processing, x then y (registers only)
    int cx = 0, cy = 0;
    float fpp = 0.f;
    if (tid < NBLK) {
        const int s = tid * W;
        unsigned mx, my;
        int c20;
        processBlock<false>(xs, s, mx, c20, ys, 0u, fpp);
        cx = c20;
        processBlock<true>(ys, s, my, c20, xs, mx, fpp);
        cy = c20;
    }

    // Phase 3: combined block reduction (4 doubles + 2 ints, 7 warps)
    double vals[4] = {(double)fdt, (double)fnx, (double)fny, (double)fpp};
    #pragma unroll
    for (int k = 0; k < 4; ++k) vals[k] = wredD(vals[k]);
    cx = wredI(cx);
    cy = wredI(cy);
    if (lane == 0) {
        #pragma unroll
        for (int k = 0; k < 4; ++k) redd[wid * 4 + k] = vals[k];
        redi[wid * 2 + 0] = cx;
        redi[wid * 2 + 1] = cy;
    }
    __syncthreads();                                   // B2

    if (tid == 0) {
        double dt = 0, nx = 0, ny = 0, pp = 0;
        int tcx = 0, tcy = 0;
        #pragma unroll
        for (int w = 0; w < NT / 32; ++w) {
            dt += redd[w * 4 + 0]; nx += redd[w * 4 + 1];
            ny += redd[w * 4 + 2]; pp += redd[w * 4 + 3];
            tcx += redi[w * 2 + 0]; tcy += redi[w * 2 + 1];
        }
        const double sd = nx - 2.0 * dt + ny;          // sum (a-b)^2
        const double mse_i = sd / (double)LEN;
        const double p2p_i = pp / (double)LEN;
        const double cosv  = dt / (sqrt(nx) * sqrt(ny));
        const double custom = (tcx != tcy) ? mse_i : 0.5 * p2p_i;  // ALPHA=1, BETA=0.5
        float4 r;
        r.x = (float)sd; r.y = (float)cosv; r.z = (float)pp; r.w = (float)custom;
        g_rowbuf[row] = r;
        __threadfence();
        s_isLast = (atomicAdd(&g_count, 1u) == BATCH - 1);
    }
    __syncthreads();                                   // B3

    // Phase 4: last CTA performs the deterministic final reduction
    if (s_isLast) {
        double s0 = 0, s1 = 0, s2 = 0, s3 = 0;
        for (int r = tid; r < BATCH; r += NT) {
            float4 p = g_rowbuf[r];
            s0 += (double)p.x; s1 += (double)p.y;
            s2 += (double)p.z; s3 += (double)p.w;
        }
        s0 = wredD(s0); s1 = wredD(s1); s2 = wredD(s2); s3 = wredD(s3);
        if (lane == 0) {
            redd[wid * 4 + 0] = s0; redd[wid * 4 + 1] = s1;
            redd[wid * 4 + 2] = s2; redd[wid * 4 + 3] = s3;
        }
        __syncthreads();
        if (tid == 0) {
            double t0 = 0, t1 = 0, t2s = 0, t3 = 0;
            #pragma unroll
            for (int w = 0; w < NT / 32; ++w) {
                t0 += redd[w * 4 + 0]; t1 += redd[w * 4 + 1];
                t2s += redd[w * 4 + 2]; t3 += redd[w * 4 + 3];
            }
            const double mse = t0 / ((double)BATCH * (double)LEN);
            out[0] = (float)(mse + t3);               // total_loss
            out[1] = (float)(t1 / (double)BATCH);     // cosine_similarity
            out[2] = (float)(t2s / (double)LEN);      // p2p_loss
            out[3] = (float)mse;                      // mse_loss
            g_count = 0;                              // reset for next replay
        }
    }
}

extern "C" void kernel_launch(void* const* d_in, const int* in_sizes, int n_in,
                              void* d_out, int out_size) {
    const float* x = (const float*)d_in[0];   // in_signal  [2048, 4096] f32
    const float* y = (const float*)d_in[1];   // ref_signal [2048, 4096] f32
    float* out = (float*)d_out;
    loss_kernel<<<BATCH, NT>>>(x, y, out);
}